// round 8
// baseline (speedup 1.0000x reference)
#include <cuda_runtime.h>
#include <cuda_bf16.h>
#include <cstdint>

#define NN 100000
#define NE 1600000
#define NG 64
#define DD 128
#define NBS 98            // ceil(100000/1024)
#define NTILE 782         // ceil(100000/128)
#define EPSX 1e-5f

// ---------------- scratch (static device globals; no allocation) ----------------
__device__ __align__(16) uint2 g_bufA[NN * 32];         // bf16 messages (row-major, 256B/node)
__device__ __align__(16) float g_bufB[NN * DD];         // gemm output fp32
__device__ __align__(16) char  g_Wbf[3 * 32768];        // bf16 weights, [n][k] layout per layer
__device__ int   g_csr[NE];
__device__ int   g_off[NN];
__device__ int   g_cur[NN];
__device__ int   g_degin[NN];
__device__ int   g_degout[NN];
__device__ float g_nsrc[NN];
__device__ float g_ndst[NN];
__device__ int   g_part[NBS];
__device__ __align__(16) float g_sum[DD];
__device__ __align__(16) float g_sq[DD];
__device__ __align__(16) float g_scale[DD];
__device__ __align__(16) float g_shift[DD];
__device__ int   g_gcnt[NG];
__device__ __align__(16) float g_hg[NG * DD];

// ---------------- helpers ----------------
__device__ __forceinline__ uint2 pack_bf16x4(float a, float b, float c, float d) {
    __nv_bfloat162 lo = __floats2bfloat162_rn(a, b);
    __nv_bfloat162 hi = __floats2bfloat162_rn(c, d);
    uint2 u;
    u.x = *reinterpret_cast<unsigned int*>(&lo);
    u.y = *reinterpret_cast<unsigned int*>(&hi);
    return u;
}

__device__ __forceinline__ uint32_t smem_u32(const void* p) {
    uint32_t a;
    asm("{ .reg .u64 t; cvta.to.shared.u64 t, %1; cvt.u32.u64 %0, t; }" : "=r"(a) : "l"(p));
    return a;
}

__device__ __forceinline__ void addmsg(float2& a0, float2& a1, uint2 m) {
    float2 f = __bfloat1622float2(*reinterpret_cast<__nv_bfloat162*>(&m.x));
    a0.x += f.x; a0.y += f.y;
    f = __bfloat1622float2(*reinterpret_cast<__nv_bfloat162*>(&m.y));
    a1.x += f.x; a1.y += f.y;
}

// ---------------- setup kernels ----------------
__global__ void k_zero() {
    int i = blockIdx.x * 256 + threadIdx.x;
    if (i < NN) { g_degin[i] = 0; g_degout[i] = 0; }
    if (i < NG) g_gcnt[i] = 0;
    if (i < NG * DD) g_hg[i] = 0.0f;
    if (i < DD) { g_sum[i] = 0.0f; g_sq[i] = 0.0f; }
}

__global__ void k_deg(const int* __restrict__ src, const int* __restrict__ dst,
                      const int* __restrict__ gids) {
    int e = blockIdx.x * 256 + threadIdx.x;
    if (e < NE) {
        atomicAdd(&g_degout[src[e]], 1);
        atomicAdd(&g_degin[dst[e]], 1);
    }
    bool valid = e < NN;
    int g = valid ? gids[e] : -1;
    int g0 = __shfl_sync(0xffffffffu, g, 0);
    if (__all_sync(0xffffffffu, g == g0)) {
        if ((threadIdx.x & 31) == 0 && g0 >= 0) atomicAdd(&g_gcnt[g0], 32);
    } else if (valid) {
        atomicAdd(&g_gcnt[g], 1);
    }
}

__global__ void k_scan1() {
    int tid = threadIdx.x;
    int gid = blockIdx.x * 1024 + tid;
    int v = (gid < NN) ? g_degin[gid] : 0;
    int lane = tid & 31, w = tid >> 5;
    int x = v;
#pragma unroll
    for (int o = 1; o < 32; o <<= 1) {
        int y = __shfl_up_sync(0xffffffffu, x, o);
        if (lane >= o) x += y;
    }
    __shared__ int ws[32];
    if (lane == 31) ws[w] = x;
    __syncthreads();
    if (w == 0) {
        int y = ws[lane];
#pragma unroll
        for (int o = 1; o < 32; o <<= 1) {
            int z = __shfl_up_sync(0xffffffffu, y, o);
            if (lane >= o) y += z;
        }
        ws[lane] = y;
    }
    __syncthreads();
    int incl = x + (w ? ws[w - 1] : 0);
    if (gid < NN) g_off[gid] = incl - v;
    if (tid == 1023) g_part[blockIdx.x] = incl;
}

// finalize offsets + norms; every block redundantly scans the 98 partials
__global__ void k_scan3() {
    __shared__ int ws[4];
    __shared__ int po;
    int tid = threadIdx.x;
    int lane = tid & 31, w2 = tid >> 5;
    int v = 0, x = 0;
    if (tid < 128) {
        v = (tid < NBS) ? g_part[tid] : 0;
        x = v;
#pragma unroll
        for (int o = 1; o < 32; o <<= 1) {
            int y = __shfl_up_sync(0xffffffffu, x, o);
            if (lane >= o) x += y;
        }
        if (lane == 31) ws[w2] = x;
    }
    __syncthreads();
    if (tid < 128) {
        int add = 0;
#pragma unroll
        for (int i = 0; i < 4; i++) if (i < w2) add += ws[i];
        if (tid == (int)blockIdx.x) po = x - v + add;   // exclusive prefix for this block
    }
    __syncthreads();
    int gid = blockIdx.x * 1024 + tid;
    if (gid < NN) {
        int o = g_off[gid] + po;
        g_off[gid] = o;
        g_cur[gid] = o;
        g_nsrc[gid] = rsqrtf((float)max(g_degout[gid], 1));
        g_ndst[gid] = rsqrtf((float)max(g_degin[gid], 1));
    }
}

__global__ void k_scatter(const int* __restrict__ src, const int* __restrict__ dst) {
    int e = blockIdx.x * 256 + threadIdx.x;
    if (e < NE) {
        int d = dst[e];
        int pos = atomicAdd(&g_cur[d], 1);
        g_csr[pos] = src[e];
    }
}

// W[k][n] fp32 -> bf16 [n][k] (B col-major for mma.sync)
__global__ void k_wconv(const float* __restrict__ W0, const float* __restrict__ W1,
                        const float* __restrict__ W2) {
    int idx = blockIdx.x * 256 + threadIdx.x;
    if (idx >= 3 * 16384) return;
    int l = idx >> 14, rem = idx & 16383;
    int k = rem >> 7, n = rem & 127;
    const float* W = (l == 0) ? W0 : ((l == 1) ? W1 : W2);
    ((__nv_bfloat16*)(g_Wbf + l * 32768))[n * 128 + k] = __float2bfloat16(W[k * 128 + n]);
}

// h0 = bf16(embed[tokens] * norm_src)
__global__ void k_embed(const int* __restrict__ tokens, const float* __restrict__ embed) {
    int idx = blockIdx.x * 256 + threadIdx.x;
    if (idx >= NN * 32) return;
    int v = idx >> 5, q = idx & 31;
    int t = tokens[v];
    float4 e = ((const float4*)embed)[t * 32 + q];
    float ns = g_nsrc[v];
    g_bufA[idx] = pack_bf16x4(e.x * ns, e.y * ns, e.z * ns, e.w * ns);
}

// ---------------- fused agg + mma.sync GEMM, fused BN stats ----------------
// Block = 128 nodes. Phase 1: warp-per-node aggregation straight into swizzled
// smem (bf16, two 64-k halves, XOR-swizzled 16B chunks). Phase 2: 8-warp MMA.
// dyn smem: XsA[16K] XsB[16K] WtA[16K] WtB[16K]
__global__ __launch_bounds__(256) void k_agg_gemm(int layer, const float* __restrict__ bias) {
    extern __shared__ char dyn[];
    char* XsA = dyn;
    char* XsB = dyn + 16384;
    char* WtA = dyn + 32768;
    char* WtB = dyn + 49152;
    __shared__ float sS[DD], sQ[DD], sB[DD];
    int tid = threadIdx.x, lane = tid & 31, w = tid >> 5;
    int base = blockIdx.x * 128;
    if (tid < DD) { sS[tid] = 0.0f; sQ[tid] = 0.0f; sB[tid] = bias[tid]; }

    // ---- stage W (32KB = 2048 uint4), swizzled ----
    const uint4* Wg = (const uint4*)(g_Wbf + layer * 32768);
#pragma unroll
    for (int i = 0; i < 8; i++) {
        int f = tid + i * 256;             // 0..2047
        int n = f >> 4, j = f & 15;        // row n, 16B chunk j
        uint4 val = Wg[f];
        char* dsth = (j < 8) ? WtA : WtB;
        *(uint4*)(dsth + n * 128 + (((j & 7) ^ (n & 7)) << 4)) = val;
    }

    // ---- phase 1: aggregation (warp per node, rows w, 8+w, ..., 120+w) ----
    {
        int ll = lane & 15;
        char* half = (lane < 16) ? XsA : XsB;
        for (int p = 0; p < 16; p++) {
            int r = p * 8 + w;
            int nid = base + r;
            uint2 pk = make_uint2(0, 0);
            if (nid < NN) {
                int off = g_off[nid];
                int deg = g_degin[nid];
                float2 a0 = make_float2(0, 0), a1 = make_float2(0, 0);
                float2 b0 = make_float2(0, 0), b1 = make_float2(0, 0);
                for (int bb = 0; bb < deg; bb += 32) {
                    int n = min(32, deg - bb);
                    int idxv = (bb + lane < deg) ? g_csr[off + bb + lane] : 0;
                    int j = 0;
                    for (; j + 3 < n; j += 4) {
                        int s0 = __shfl_sync(0xffffffffu, idxv, j);
                        int s1 = __shfl_sync(0xffffffffu, idxv, j + 1);
                        int s2 = __shfl_sync(0xffffffffu, idxv, j + 2);
                        int s3 = __shfl_sync(0xffffffffu, idxv, j + 3);
                        uint2 m0 = g_bufA[s0 * 32 + lane];
                        uint2 m1 = g_bufA[s1 * 32 + lane];
                        uint2 m2 = g_bufA[s2 * 32 + lane];
                        uint2 m3 = g_bufA[s3 * 32 + lane];
                        addmsg(a0, a1, m0);
                        addmsg(b0, b1, m1);
                        addmsg(a0, a1, m2);
                        addmsg(b0, b1, m3);
                    }
                    for (; j < n; j++) {
                        int s0 = __shfl_sync(0xffffffffu, idxv, j);
                        uint2 m0 = g_bufA[s0 * 32 + lane];
                        addmsg(a0, a1, m0);
                    }
                }
                float nd = g_ndst[nid];
                pk = pack_bf16x4((a0.x + b0.x) * nd, (a0.y + b0.y) * nd,
                                 (a1.x + b1.x) * nd, (a1.y + b1.y) * nd);
            }
            *(uint2*)(half + r * 128 + (((ll >> 1) ^ (r & 7)) << 4) + (ll & 1) * 8) = pk;
        }
    }
    __syncthreads();

    // ---- phase 2: MMA (warp w: rows [w*16, w*16+16), all 128 cols) ----
    float d[16][4];
#pragma unroll
    for (int t = 0; t < 16; t++)
#pragma unroll
        for (int j = 0; j < 4; j++) d[t][j] = 0.0f;

    int wrow = w * 16;
    int la7 = lane & 7;
    int axoff = lane >> 4;                 // 0/1: A k-subchunk
    int bsel = (lane >> 3) & 1;            // 0/1: B k-subchunk
    char* arowA = XsA + (wrow + (lane & 15)) * 128;
    char* arowB = XsB + (wrow + (lane & 15)) * 128;
    char* browA = WtA + la7 * 128;
    char* browB = WtB + la7 * 128;

#pragma unroll
    for (int ks = 0; ks < 8; ks++) {
        int ksl = ks & 3;
        char* ar = (ks < 4) ? arowA : arowB;
        char* br = (ks < 4) ? browA : browB;
        uint32_t a0, a1, a2, a3;
        uint32_t aaddr = smem_u32(ar + (((ksl * 2 + axoff) ^ la7) << 4));
        asm volatile("ldmatrix.sync.aligned.m8n8.x4.shared.b16 {%0,%1,%2,%3}, [%4];"
                     : "=r"(a0), "=r"(a1), "=r"(a2), "=r"(a3) : "r"(aaddr));
        uint32_t baddr0 = smem_u32(br + (((ksl * 2 + bsel) ^ la7) << 4));
#pragma unroll
        for (int t = 0; t < 16; t++) {
            uint32_t b0, b1;
            asm volatile("ldmatrix.sync.aligned.m8n8.x2.shared.b16 {%0,%1}, [%2];"
                         : "=r"(b0), "=r"(b1) : "r"(baddr0 + t * 1024));
            asm volatile(
                "mma.sync.aligned.m16n8k16.row.col.f32.bf16.bf16.f32 "
                "{%0,%1,%2,%3}, {%4,%5,%6,%7}, {%8,%9}, {%0,%1,%2,%3};"
                : "+f"(d[t][0]), "+f"(d[t][1]), "+f"(d[t][2]), "+f"(d[t][3])
                : "r"(a0), "r"(a1), "r"(a2), "r"(a3), "r"(b0), "r"(b1));
        }
    }

    // ---- epilogue: bias + store + per-column stats ----
    int r0 = base + wrow + (lane >> 2);
    int r1 = r0 + 8;
    bool v0 = r0 < NN, v1 = r1 < NN;
#pragma unroll
    for (int t = 0; t < 16; t++) {
        int c0 = t * 8 + (lane & 3) * 2;
        float bb0 = sB[c0], bb1 = sB[c0 + 1];
        float d0 = v0 ? d[t][0] + bb0 : 0.0f;
        float d1 = v0 ? d[t][1] + bb1 : 0.0f;
        float d2 = v1 ? d[t][2] + bb0 : 0.0f;
        float d3 = v1 ? d[t][3] + bb1 : 0.0f;
        if (v0) *(float2*)&g_bufB[(size_t)r0 * DD + c0] = make_float2(d0, d1);
        if (v1) *(float2*)&g_bufB[(size_t)r1 * DD + c0] = make_float2(d2, d3);
        float s0 = d0 + d2, s1 = d1 + d3;
        float q0 = d0 * d0 + d2 * d2, q1 = d1 * d1 + d3 * d3;
#pragma unroll
        for (int o = 4; o < 32; o <<= 1) {
            s0 += __shfl_xor_sync(0xffffffffu, s0, o);
            s1 += __shfl_xor_sync(0xffffffffu, s1, o);
            q0 += __shfl_xor_sync(0xffffffffu, q0, o);
            q1 += __shfl_xor_sync(0xffffffffu, q1, o);
        }
        if (lane < 4) {
            atomicAdd(&sS[c0], s0);
            atomicAdd(&sS[c0 + 1], s1);
            atomicAdd(&sQ[c0], q0);
            atomicAdd(&sQ[c0 + 1], q1);
        }
    }
    __syncthreads();
    if (tid < DD) {
        atomicAdd(&g_sum[tid], sS[tid]);
        atomicAdd(&g_sq[tid], sQ[tid]);
    }
}

// finalize BN affine, then re-zero stat accumulators for the next layer
__global__ void k_bnfinal(const float* __restrict__ gamma, const float* __restrict__ beta) {
    int c = threadIdx.x;
    const float invn = 1.0f / (float)NN;
    float mu = g_sum[c] * invn;
    float var = g_sq[c] * invn - mu * mu;
    var = fmaxf(var, 0.0f);
    float sc = gamma[c] * rsqrtf(var + EPSX);
    g_scale[c] = sc;
    g_shift[c] = beta[c] - mu * sc;
    g_sum[c] = 0.0f;
    g_sq[c] = 0.0f;
}

// layers 0/1: bufA = bf16(relu(bn(bufB)) * norm_src)
__global__ void k_apply() {
    int idx = blockIdx.x * 256 + threadIdx.x;
    if (idx >= NN * 32) return;
    int v = idx >> 5, q = idx & 31;
    float4 y = ((const float4*)g_bufB)[idx];
    float4 sc = ((const float4*)g_scale)[q];
    float4 sh = ((const float4*)g_shift)[q];
    float ns = g_nsrc[v];
    float rx = fmaxf(fmaf(y.x, sc.x, sh.x), 0.0f) * ns;
    float ry = fmaxf(fmaf(y.y, sc.y, sh.y), 0.0f) * ns;
    float rz = fmaxf(fmaf(y.z, sc.z, sh.z), 0.0f) * ns;
    float rw = fmaxf(fmaf(y.w, sc.w, sh.w), 0.0f) * ns;
    g_bufA[idx] = pack_bf16x4(rx, ry, rz, rw);
}

// layer 2: relu(bn(bufB)) pooled per graph (warp-reduced; graph_ids sorted)
__global__ void k_pool(const int* __restrict__ gids) {
    int w = threadIdx.x >> 5, lane = threadIdx.x & 31;
    int v = blockIdx.x * 32 + lane;
    bool valid = v < NN;
    int g = valid ? gids[v] : 0;
    int g0 = __shfl_sync(0xffffffffu, g, 0);
    bool uni = __all_sync(0xffffffffu, valid && g == g0);
#pragma unroll
    for (int qq = 0; qq < 4; qq++) {
        int q = w * 4 + qq;
        float4 val = make_float4(0, 0, 0, 0);
        if (valid) {
            float4 y = ((const float4*)g_bufB)[v * 32 + q];
            float4 sc = ((const float4*)g_scale)[q];
            float4 sh = ((const float4*)g_shift)[q];
            val.x = fmaxf(fmaf(y.x, sc.x, sh.x), 0.0f);
            val.y = fmaxf(fmaf(y.y, sc.y, sh.y), 0.0f);
            val.z = fmaxf(fmaf(y.z, sc.z, sh.z), 0.0f);
            val.w = fmaxf(fmaf(y.w, sc.w, sh.w), 0.0f);
        }
        if (uni) {
#pragma unroll
            for (int o = 16; o; o >>= 1) {
                val.x += __shfl_xor_sync(0xffffffffu, val.x, o);
                val.y += __shfl_xor_sync(0xffffffffu, val.y, o);
                val.z += __shfl_xor_sync(0xffffffffu, val.z, o);
                val.w += __shfl_xor_sync(0xffffffffu, val.w, o);
            }
            if (lane == 0) {
                float* p = &g_hg[g0 * DD + q * 4];
                atomicAdd(p + 0, val.x);
                atomicAdd(p + 1, val.y);
                atomicAdd(p + 2, val.z);
                atomicAdd(p + 3, val.w);
            }
        } else if (valid) {
            float* p = &g_hg[g * DD + q * 4];
            atomicAdd(p + 0, val.x);
            atomicAdd(p + 1, val.y);
            atomicAdd(p + 2, val.z);
            atomicAdd(p + 3, val.w);
        }
    }
}

// head: mean -> fc1 relu -> fc2   (one block per graph, 64 threads)
__global__ void k_head(const float* __restrict__ fcW1, const float* __restrict__ fcb1,
                       const float* __restrict__ fcW2, const float* __restrict__ fcb2,
                       float* __restrict__ out) {
    int g = blockIdx.x, t = threadIdx.x;
    __shared__ float hg[DD];
    __shared__ float s0[64], s1[64];
    float inv = 1.0f / (float)max(g_gcnt[g], 1);
    for (int k = t; k < DD; k += 64) hg[k] = g_hg[g * DD + k] * inv;
    __syncthreads();
    float z = fcb1[t];
#pragma unroll
    for (int k = 0; k < DD; k++) z = fmaf(hg[k], fcW1[k * 64 + t], z);
    z = fmaxf(z, 0.0f);
    s0[t] = z * fcW2[t * 2 + 0];
    s1[t] = z * fcW2[t * 2 + 1];
    __syncthreads();
    if (t == 0) {
        float a = 0.0f, b = 0.0f;
        for (int j = 0; j < 64; j++) { a += s0[j]; b += s1[j]; }
        out[g * 2 + 0] = a + fcb2[0];
        out[g * 2 + 1] = b + fcb2[1];
    }
}

// ---------------- launch ----------------
extern "C" void kernel_launch(void* const* d_in, const int* in_sizes, int n_in,
                              void* d_out, int out_size) {
    const int* tokens = (const int*)d_in[0];
    const int* src    = (const int*)d_in[1];
    const int* dst    = (const int*)d_in[2];
    const int* gids   = (const int*)d_in[3];
    const float* embed = (const float*)d_in[4];
    const float* W[3]  = {(const float*)d_in[5], (const float*)d_in[9],  (const float*)d_in[13]};
    const float* bW[3] = {(const float*)d_in[6], (const float*)d_in[10], (const float*)d_in[14]};
    const float* ga[3] = {(const float*)d_in[7], (const float*)d_in[11], (const float*)d_in[15]};
    const float* be[3] = {(const float*)d_in[8], (const float*)d_in[12], (const float*)d_in[16]};
    const float* fcW1 = (const float*)d_in[17];
    const float* fcb1 = (const float*)d_in[18];
    const float* fcW2 = (const float*)d_in[19];
    const float* fcb2 = (const float*)d_in[20];
    float* out = (float*)d_out;

    cudaFuncSetAttribute(k_agg_gemm, cudaFuncAttributeMaxDynamicSharedMemorySize, 65536);

    k_zero<<<391, 256>>>();
    k_deg<<<6250, 256>>>(src, dst, gids);
    k_scan1<<<NBS, 1024>>>();
    k_scan3<<<NBS, 1024>>>();
    k_scatter<<<6250, 256>>>(src, dst);
    k_wconv<<<192, 256>>>(W[0], W[1], W[2]);
    k_embed<<<12500, 256>>>(tokens, embed);

    for (int l = 0; l < 3; l++) {
        k_agg_gemm<<<NTILE, 256, 65536>>>(l, bW[l]);
        k_bnfinal<<<1, 128>>>(ga[l], be[l]);
        if (l < 2)
            k_apply<<<12500, 256>>>();
        else
            k_pool<<<3125, 256>>>(gids);
    }
    k_head<<<64, 64>>>(fcW1, fcb1, fcW2, fcb2, out);
}

// round 9
// speedup vs baseline: 1.2484x; 1.2484x over previous
#include <cuda_runtime.h>
#include <cuda_bf16.h>
#include <cstdint>

#define NN 100000
#define NE 1600000
#define NG 64
#define DD 128
#define NBS 98            // ceil(100000/1024)
#define NTILE 782         // ceil(100000/128)
#define EPSX 1e-5f

// ---------------- scratch (static device globals; no allocation) ----------------
__device__ __align__(16) uint2 g_bufA[NN * 32];         // bf16 messages (row-major, 256B/node)
__device__ __align__(16) float g_bufB[NN * DD];         // gemm output fp32
__device__ __align__(16) uint2 g_bufX[NTILE * 128 * 32];// bf16 agg output rows (pad rows zeroed)
__device__ __align__(16) char  g_Wbf[3 * 32768];        // bf16 weights, [n][k] layout per layer
__device__ int   g_csr[NE];
__device__ int   g_off[NN];
__device__ int   g_cur[NN];
__device__ int   g_degin[NN];
__device__ int   g_degout[NN];
__device__ float g_nsrc[NN];
__device__ float g_ndst[NN];
__device__ int   g_part[NBS];
__device__ __align__(16) float g_sum[3 * DD];           // per-layer BN stats
__device__ __align__(16) float g_sq[3 * DD];
__device__ int   g_gcnt[NG];
__device__ __align__(16) float g_hg[NG * DD];

// ---------------- helpers ----------------
__device__ __forceinline__ uint2 pack_bf16x4(float a, float b, float c, float d) {
    __nv_bfloat162 lo = __floats2bfloat162_rn(a, b);
    __nv_bfloat162 hi = __floats2bfloat162_rn(c, d);
    uint2 u;
    u.x = *reinterpret_cast<unsigned int*>(&lo);
    u.y = *reinterpret_cast<unsigned int*>(&hi);
    return u;
}

__device__ __forceinline__ uint32_t smem_u32(const void* p) {
    uint32_t a;
    asm("{ .reg .u64 t; cvta.to.shared.u64 t, %1; cvt.u32.u64 %0, t; }" : "=r"(a) : "l"(p));
    return a;
}

__device__ __forceinline__ void addmsg(float2& a0, float2& a1, uint2 m) {
    float2 f = __bfloat1622float2(*reinterpret_cast<__nv_bfloat162*>(&m.x));
    a0.x += f.x; a0.y += f.y;
    f = __bfloat1622float2(*reinterpret_cast<__nv_bfloat162*>(&m.y));
    a1.x += f.x; a1.y += f.y;
}

// compute BN affine for `layer` into smem ssc/ssh (first 128 threads; caller syncs)
__device__ __forceinline__ void bn_affine(int layer, const float* gamma, const float* beta,
                                          float* ssc, float* ssh, int tid) {
    if (tid < DD) {
        const float invn = 1.0f / (float)NN;
        float mu = g_sum[layer * DD + tid] * invn;
        float var = g_sq[layer * DD + tid] * invn - mu * mu;
        var = fmaxf(var, 0.0f);
        float sc = gamma[tid] * rsqrtf(var + EPSX);
        ssc[tid] = sc;
        ssh[tid] = beta[tid] - mu * sc;
    }
}

// ---------------- setup kernels ----------------
// zero everything + convert W to bf16 [n][k]
__global__ void k_zero(const float* __restrict__ W0, const float* __restrict__ W1,
                       const float* __restrict__ W2) {
    int i = blockIdx.x * 256 + threadIdx.x;
    if (i < NN) { g_degin[i] = 0; g_degout[i] = 0; }
    if (i < NG) g_gcnt[i] = 0;
    if (i < NG * DD) g_hg[i] = 0.0f;
    if (i < 3 * DD) { g_sum[i] = 0.0f; g_sq[i] = 0.0f; }
    if (i < (NTILE * 128 - NN) * 32) g_bufX[NN * 32 + i] = make_uint2(0, 0);  // pad rows
    if (i < 3 * 16384) {
        int l = i >> 14, rem = i & 16383;
        int k = rem >> 7, n = rem & 127;
        const float* W = (l == 0) ? W0 : ((l == 1) ? W1 : W2);
        ((__nv_bfloat16*)(g_Wbf + l * 32768))[n * 128 + k] = __float2bfloat16(W[k * 128 + n]);
    }
}

__global__ void k_deg(const int* __restrict__ src, const int* __restrict__ dst,
                      const int* __restrict__ gids) {
    int e = blockIdx.x * 256 + threadIdx.x;
    if (e < NE) {
        atomicAdd(&g_degout[src[e]], 1);
        atomicAdd(&g_degin[dst[e]], 1);
    }
    bool valid = e < NN;
    int g = valid ? gids[e] : -1;
    int g0 = __shfl_sync(0xffffffffu, g, 0);
    if (__all_sync(0xffffffffu, g == g0)) {
        if ((threadIdx.x & 31) == 0 && g0 >= 0) atomicAdd(&g_gcnt[g0], 32);
    } else if (valid) {
        atomicAdd(&g_gcnt[g], 1);
    }
}

__global__ void k_scan1() {
    int tid = threadIdx.x;
    int gid = blockIdx.x * 1024 + tid;
    int v = (gid < NN) ? g_degin[gid] : 0;
    int lane = tid & 31, w = tid >> 5;
    int x = v;
#pragma unroll
    for (int o = 1; o < 32; o <<= 1) {
        int y = __shfl_up_sync(0xffffffffu, x, o);
        if (lane >= o) x += y;
    }
    __shared__ int ws[32];
    if (lane == 31) ws[w] = x;
    __syncthreads();
    if (w == 0) {
        int y = ws[lane];
#pragma unroll
        for (int o = 1; o < 32; o <<= 1) {
            int z = __shfl_up_sync(0xffffffffu, y, o);
            if (lane >= o) y += z;
        }
        ws[lane] = y;
    }
    __syncthreads();
    int incl = x + (w ? ws[w - 1] : 0);
    if (gid < NN) g_off[gid] = incl - v;
    if (tid == 1023) g_part[blockIdx.x] = incl;
}

// finalize offsets + norms; every block redundantly scans the 98 partials
__global__ void k_scan3() {
    __shared__ int ws[4];
    __shared__ int po;
    int tid = threadIdx.x;
    int lane = tid & 31, w2 = tid >> 5;
    int v = 0, x = 0;
    if (tid < 128) {
        v = (tid < NBS) ? g_part[tid] : 0;
        x = v;
#pragma unroll
        for (int o = 1; o < 32; o <<= 1) {
            int y = __shfl_up_sync(0xffffffffu, x, o);
            if (lane >= o) x += y;
        }
        if (lane == 31) ws[w2] = x;
    }
    __syncthreads();
    if (tid < 128) {
        int add = 0;
#pragma unroll
        for (int i = 0; i < 4; i++) if (i < w2) add += ws[i];
        if (tid == (int)blockIdx.x) po = x - v + add;   // exclusive prefix for this block
    }
    __syncthreads();
    int gid = blockIdx.x * 1024 + tid;
    if (gid < NN) {
        int o = g_off[gid] + po;
        g_off[gid] = o;
        g_cur[gid] = o;
        g_nsrc[gid] = rsqrtf((float)max(g_degout[gid], 1));
        g_ndst[gid] = rsqrtf((float)max(g_degin[gid], 1));
    }
}

__global__ void k_scatter(const int* __restrict__ src, const int* __restrict__ dst) {
    int e = blockIdx.x * 256 + threadIdx.x;
    if (e < NE) {
        int d = dst[e];
        int pos = atomicAdd(&g_cur[d], 1);
        g_csr[pos] = src[e];
    }
}

// h0 = bf16(embed[tokens] * norm_src)
__global__ void k_embed(const int* __restrict__ tokens, const float* __restrict__ embed) {
    int idx = blockIdx.x * 256 + threadIdx.x;
    if (idx >= NN * 32) return;
    int v = idx >> 5, q = idx & 31;
    int t = tokens[v];
    float4 e = ((const float4*)embed)[t * 32 + q];
    float ns = g_nsrc[v];
    g_bufA[idx] = pack_bf16x4(e.x * ns, e.y * ns, e.z * ns, e.w * ns);
}

// ---------------- per-layer kernels ----------------
// agg[v] = norm_dst[v] * sum bufA[src]; bf16 output row-major into g_bufX
__global__ void k_agg() {
    int nid = blockIdx.x * 8 + (threadIdx.x >> 5);
    int lane = threadIdx.x & 31;
    if (nid >= NN) return;
    int off = g_off[nid];
    int deg = g_degin[nid];
    float2 a0 = make_float2(0, 0), a1 = make_float2(0, 0);
    float2 b0 = make_float2(0, 0), b1 = make_float2(0, 0);
    for (int base = 0; base < deg; base += 32) {
        int n = min(32, deg - base);
        int idx = (base + lane < deg) ? g_csr[off + base + lane] : 0;
        int j = 0;
        for (; j + 3 < n; j += 4) {
            int s0 = __shfl_sync(0xffffffffu, idx, j);
            int s1 = __shfl_sync(0xffffffffu, idx, j + 1);
            int s2 = __shfl_sync(0xffffffffu, idx, j + 2);
            int s3 = __shfl_sync(0xffffffffu, idx, j + 3);
            uint2 m0 = g_bufA[s0 * 32 + lane];
            uint2 m1 = g_bufA[s1 * 32 + lane];
            uint2 m2 = g_bufA[s2 * 32 + lane];
            uint2 m3 = g_bufA[s3 * 32 + lane];
            addmsg(a0, a1, m0);
            addmsg(b0, b1, m1);
            addmsg(a0, a1, m2);
            addmsg(b0, b1, m3);
        }
        for (; j < n; j++) {
            int s0 = __shfl_sync(0xffffffffu, idx, j);
            uint2 m0 = g_bufA[s0 * 32 + lane];
            addmsg(a0, a1, m0);
        }
    }
    float nd = g_ndst[nid];
    g_bufX[nid * 32 + lane] = pack_bf16x4((a0.x + b0.x) * nd, (a0.y + b0.y) * nd,
                                          (a1.x + b1.x) * nd, (a1.y + b1.y) * nd);
}

// ---------------- mma.sync GEMM: bufB = X @ W + b, fused BN stats ----------------
// 256 threads = 8 warps; block tile 128 rows x 128 cols; K in 2 halves of 64.
#define XST 144   // padded smem row stride bytes (128B data + 16) -> conflict-free ldmatrix

__global__ __launch_bounds__(256) void k_gemm_mma(int layer, const float* __restrict__ bias) {
    __shared__ __align__(16) char Xs[128 * XST];
    __shared__ __align__(16) char Wt[128 * XST];
    __shared__ float sS[DD], sQ[DD], sB[DD];
    int tid = threadIdx.x, lane = tid & 31, w = tid >> 5;
    int base = blockIdx.x * 128;
    if (tid < DD) { sS[tid] = 0.0f; sQ[tid] = 0.0f; sB[tid] = bias[tid]; }

    float d[16][4];
#pragma unroll
    for (int t = 0; t < 16; t++)
#pragma unroll
        for (int j = 0; j < 4; j++) d[t][j] = 0.0f;

    const uint4* Xg = (const uint4*)g_bufX + (size_t)base * 16;   // 16 uint4 per row
    const uint4* Wg = (const uint4*)(g_Wbf + layer * 32768);

    int wrow = w * 16;
    uint32_t a_base = smem_u32(Xs + (wrow + (lane & 15)) * XST + (lane >> 4) * 16);
    uint32_t b_base = smem_u32(Wt + (lane & 7) * XST + ((lane >> 3) & 1) * 16);

#pragma unroll
    for (int kh = 0; kh < 2; kh++) {
        // stage 64-k half of X and W: 1024 uint4 each, 256 threads x 4
#pragma unroll
        for (int i = 0; i < 4; i++) {
            int f = tid + i * 256;
            int r = f >> 3, j = f & 7;
            *(uint4*)(Xs + r * XST + j * 16) = Xg[r * 16 + kh * 8 + j];
            *(uint4*)(Wt + r * XST + j * 16) = Wg[r * 16 + kh * 8 + j];
        }
        __syncthreads();
#pragma unroll
        for (int ks = 0; ks < 4; ks++) {
            uint32_t a0, a1, a2, a3;
            asm volatile("ldmatrix.sync.aligned.m8n8.x4.shared.b16 {%0,%1,%2,%3}, [%4];"
                         : "=r"(a0), "=r"(a1), "=r"(a2), "=r"(a3)
                         : "r"(a_base + ks * 32));
#pragma unroll
            for (int t = 0; t < 16; t++) {
                uint32_t b0, b1;
                asm volatile("ldmatrix.sync.aligned.m8n8.x2.shared.b16 {%0,%1}, [%2];"
                             : "=r"(b0), "=r"(b1)
                             : "r"(b_base + t * 8 * XST + ks * 32));
                asm volatile(
                    "mma.sync.aligned.m16n8k16.row.col.f32.bf16.bf16.f32 "
                    "{%0,%1,%2,%3}, {%4,%5,%6,%7}, {%8,%9}, {%0,%1,%2,%3};"
                    : "+f"(d[t][0]), "+f"(d[t][1]), "+f"(d[t][2]), "+f"(d[t][3])
                    : "r"(a0), "r"(a1), "r"(a2), "r"(a3), "r"(b0), "r"(b1));
            }
        }
        __syncthreads();
    }

    // epilogue: bias + store + per-column stats
    int r0 = base + wrow + (lane >> 2);
    int r1 = r0 + 8;
    bool v0 = r0 < NN, v1 = r1 < NN;
#pragma unroll
    for (int t = 0; t < 16; t++) {
        int c0 = t * 8 + (lane & 3) * 2;
        float bb0 = sB[c0], bb1 = sB[c0 + 1];
        float d0 = v0 ? d[t][0] + bb0 : 0.0f;
        float d1 = v0 ? d[t][1] + bb1 : 0.0f;
        float d2 = v1 ? d[t][2] + bb0 : 0.0f;
        float d3 = v1 ? d[t][3] + bb1 : 0.0f;
        if (v0) *(float2*)&g_bufB[(size_t)r0 * DD + c0] = make_float2(d0, d1);
        if (v1) *(float2*)&g_bufB[(size_t)r1 * DD + c0] = make_float2(d2, d3);
        float s0 = d0 + d2, s1 = d1 + d3;
        float q0 = d0 * d0 + d2 * d2, q1 = d1 * d1 + d3 * d3;
#pragma unroll
        for (int o = 4; o < 32; o <<= 1) {
            s0 += __shfl_xor_sync(0xffffffffu, s0, o);
            s1 += __shfl_xor_sync(0xffffffffu, s1, o);
            q0 += __shfl_xor_sync(0xffffffffu, q0, o);
            q1 += __shfl_xor_sync(0xffffffffu, q1, o);
        }
        if (lane < 4) {
            atomicAdd(&sS[c0], s0);
            atomicAdd(&sS[c0 + 1], s1);
            atomicAdd(&sQ[c0], q0);
            atomicAdd(&sQ[c0 + 1], q1);
        }
    }
    __syncthreads();
    if (tid < DD) {
        atomicAdd(&g_sum[layer * DD + tid], sS[tid]);
        atomicAdd(&g_sq[layer * DD + tid], sQ[tid]);
    }
}

// layers 0/1: bufA = bf16(relu(bn(bufB)) * norm_src)  (BN affine computed per block)
__global__ void k_apply(int layer, const float* __restrict__ gamma,
                        const float* __restrict__ beta) {
    __shared__ __align__(16) float ssc[DD], ssh[DD];
    int tid = threadIdx.x;
    bn_affine(layer, gamma, beta, ssc, ssh, tid);
    __syncthreads();
    int idx = blockIdx.x * 256 + tid;
    if (idx >= NN * 32) return;
    int v = idx >> 5, q = idx & 31;
    float4 y = ((const float4*)g_bufB)[idx];
    float4 sc = ((const float4*)ssc)[q];
    float4 sh = ((const float4*)ssh)[q];
    float ns = g_nsrc[v];
    float rx = fmaxf(fmaf(y.x, sc.x, sh.x), 0.0f) * ns;
    float ry = fmaxf(fmaf(y.y, sc.y, sh.y), 0.0f) * ns;
    float rz = fmaxf(fmaf(y.z, sc.z, sh.z), 0.0f) * ns;
    float rw = fmaxf(fmaf(y.w, sc.w, sh.w), 0.0f) * ns;
    g_bufA[idx] = pack_bf16x4(rx, ry, rz, rw);
}

// layer 2: relu(bn(bufB)) pooled per graph (warp-reduced; graph_ids sorted)
__global__ void k_pool(const int* __restrict__ gids, const float* __restrict__ gamma,
                       const float* __restrict__ beta) {
    __shared__ __align__(16) float ssc[DD], ssh[DD];
    int tid = threadIdx.x;
    bn_affine(2, gamma, beta, ssc, ssh, tid);
    __syncthreads();
    int w = tid >> 5, lane = tid & 31;
    int v = blockIdx.x * 32 + lane;
    bool valid = v < NN;
    int g = valid ? gids[v] : 0;
    int g0 = __shfl_sync(0xffffffffu, g, 0);
    bool uni = __all_sync(0xffffffffu, valid && g == g0);
#pragma unroll
    for (int qq = 0; qq < 4; qq++) {
        int q = w * 4 + qq;
        float4 val = make_float4(0, 0, 0, 0);
        if (valid) {
            float4 y = ((const float4*)g_bufB)[v * 32 + q];
            float4 sc = ((const float4*)ssc)[q];
            float4 sh = ((const float4*)ssh)[q];
            val.x = fmaxf(fmaf(y.x, sc.x, sh.x), 0.0f);
            val.y = fmaxf(fmaf(y.y, sc.y, sh.y), 0.0f);
            val.z = fmaxf(fmaf(y.z, sc.z, sh.z), 0.0f);
            val.w = fmaxf(fmaf(y.w, sc.w, sh.w), 0.0f);
        }
        if (uni) {
#pragma unroll
            for (int o = 16; o; o >>= 1) {
                val.x += __shfl_xor_sync(0xffffffffu, val.x, o);
                val.y += __shfl_xor_sync(0xffffffffu, val.y, o);
                val.z += __shfl_xor_sync(0xffffffffu, val.z, o);
                val.w += __shfl_xor_sync(0xffffffffu, val.w, o);
            }
            if (lane == 0) {
                float* p = &g_hg[g0 * DD + q * 4];
                atomicAdd(p + 0, val.x);
                atomicAdd(p + 1, val.y);
                atomicAdd(p + 2, val.z);
                atomicAdd(p + 3, val.w);
            }
        } else if (valid) {
            float* p = &g_hg[g * DD + q * 4];
            atomicAdd(p + 0, val.x);
            atomicAdd(p + 1, val.y);
            atomicAdd(p + 2, val.z);
            atomicAdd(p + 3, val.w);
        }
    }
}

// head: mean -> fc1 relu -> fc2   (one block per graph, 64 threads)
__global__ void k_head(const float* __restrict__ fcW1, const float* __restrict__ fcb1,
                       const float* __restrict__ fcW2, const float* __restrict__ fcb2,
                       float* __restrict__ out) {
    int g = blockIdx.x, t = threadIdx.x;
    __shared__ float hg[DD];
    __shared__ float s0[64], s1[64];
    float inv = 1.0f / (float)max(g_gcnt[g], 1);
    for (int k = t; k < DD; k += 64) hg[k] = g_hg[g * DD + k] * inv;
    __syncthreads();
    float z = fcb1[t];
#pragma unroll
    for (int k = 0; k < DD; k++) z = fmaf(hg[k], fcW1[k * 64 + t], z);
    z = fmaxf(z, 0.0f);
    s0[t] = z * fcW2[t * 2 + 0];
    s1[t] = z * fcW2[t * 2 + 1];
    __syncthreads();
    if (t == 0) {
        float a = 0.0f, b = 0.0f;
        for (int j = 0; j < 64; j++) { a += s0[j]; b += s1[j]; }
        out[g * 2 + 0] = a + fcb2[0];
        out[g * 2 + 1] = b + fcb2[1];
    }
}

// ---------------- launch ----------------
extern "C" void kernel_launch(void* const* d_in, const int* in_sizes, int n_in,
                              void* d_out, int out_size) {
    const int* tokens = (const int*)d_in[0];
    const int* src    = (const int*)d_in[1];
    const int* dst    = (const int*)d_in[2];
    const int* gids   = (const int*)d_in[3];
    const float* embed = (const float*)d_in[4];
    const float* W[3]  = {(const float*)d_in[5], (const float*)d_in[9],  (const float*)d_in[13]};
    const float* bW[3] = {(const float*)d_in[6], (const float*)d_in[10], (const float*)d_in[14]};
    const float* ga[3] = {(const float*)d_in[7], (const float*)d_in[11], (const float*)d_in[15]};
    const float* be[3] = {(const float*)d_in[8], (const float*)d_in[12], (const float*)d_in[16]};
    const float* fcW1 = (const float*)d_in[17];
    const float* fcb1 = (const float*)d_in[18];
    const float* fcW2 = (const float*)d_in[19];
    const float* fcb2 = (const float*)d_in[20];
    float* out = (float*)d_out;

    k_zero<<<391, 256>>>(W[0], W[1], W[2]);
    k_deg<<<6250, 256>>>(src, dst, gids);
    k_scan1<<<NBS, 1024>>>();
    k_scan3<<<NBS, 1024>>>();
    k_scatter<<<6250, 256>>>(src, dst);
    k_embed<<<12500, 256>>>(tokens, embed);

    for (int l = 0; l < 3; l++) {
        k_agg<<<12500, 256>>>();
        k_gemm_mma<<<NTILE, 256>>>(l, bW[l]);
        if (l < 2)
            k_apply<<<12500, 256>>>(l, ga[l], be[l]);
        else
            k_pool<<<3125, 256>>>(gids, ga[2], be[2]);
    }
    k_head<<<64, 64>>>(fcW1, fcb1, fcW2, fcb2, out);
}

// round 10
// speedup vs baseline: 1.2555x; 1.0056x over previous
#include <cuda_runtime.h>
#include <cuda_bf16.h>
#include <cstdint>

#define NN 100000
#define NE 1600000
#define NG 64
#define DD 128
#define NBS 98            // ceil(100000/1024)
#define NTILE 782         // ceil(100000/128)
#define EPSX 1e-5f

// ---------------- scratch (static device globals; no allocation) ----------------
__device__ __align__(16) uint2 g_bufA[NN * 32];         // bf16 messages (row-major, 256B/node)
__device__ __align__(16) uint2 g_bufB[NN * 32];         // bf16 gemm output (256B/node)
__device__ __align__(16) uint2 g_bufX[NTILE * 128 * 32];// bf16 agg output rows (pad rows zeroed)
__device__ __align__(16) char  g_Wbf[3 * 32768];        // bf16 weights, [n][k] layout per layer
__device__ int   g_csr[NE];
__device__ int   g_off[NN];
__device__ int   g_cur[NN];
__device__ int   g_degin[NN];
__device__ int   g_degout[NN];
__device__ float g_nsrc[NN];
__device__ float g_ndst[NN];
__device__ int   g_part[NBS];
__device__ __align__(16) float g_sum[3 * DD];           // per-layer BN stats
__device__ __align__(16) float g_sq[3 * DD];
__device__ int   g_gcnt[NG];
__device__ __align__(16) float g_hg[NG * DD];

// ---------------- helpers ----------------
__device__ __forceinline__ uint2 pack_bf16x4(float a, float b, float c, float d) {
    __nv_bfloat162 lo = __floats2bfloat162_rn(a, b);
    __nv_bfloat162 hi = __floats2bfloat162_rn(c, d);
    uint2 u;
    u.x = *reinterpret_cast<unsigned int*>(&lo);
    u.y = *reinterpret_cast<unsigned int*>(&hi);
    return u;
}

__device__ __forceinline__ float4 unpack_bf16x4(uint2 u) {
    float2 lo = __bfloat1622float2(*reinterpret_cast<__nv_bfloat162*>(&u.x));
    float2 hi = __bfloat1622float2(*reinterpret_cast<__nv_bfloat162*>(&u.y));
    return make_float4(lo.x, lo.y, hi.x, hi.y);
}

__device__ __forceinline__ uint32_t smem_u32(const void* p) {
    uint32_t a;
    asm("{ .reg .u64 t; cvta.to.shared.u64 t, %1; cvt.u32.u64 %0, t; }" : "=r"(a) : "l"(p));
    return a;
}

__device__ __forceinline__ void addmsg(float2& a0, float2& a1, uint2 m) {
    float2 f = __bfloat1622float2(*reinterpret_cast<__nv_bfloat162*>(&m.x));
    a0.x += f.x; a0.y += f.y;
    f = __bfloat1622float2(*reinterpret_cast<__nv_bfloat162*>(&m.y));
    a1.x += f.x; a1.y += f.y;
}

// compute BN affine for `layer` into smem ssc/ssh (first 128 threads; caller syncs)
__device__ __forceinline__ void bn_affine(int layer, const float* gamma, const float* beta,
                                          float* ssc, float* ssh, int tid) {
    if (tid < DD) {
        const float invn = 1.0f / (float)NN;
        float mu = g_sum[layer * DD + tid] * invn;
        float var = g_sq[layer * DD + tid] * invn - mu * mu;
        var = fmaxf(var, 0.0f);
        float sc = gamma[tid] * rsqrtf(var + EPSX);
        ssc[tid] = sc;
        ssh[tid] = beta[tid] - mu * sc;
    }
}

// ---------------- setup kernels ----------------
// zero everything + convert W to bf16 [n][k]
__global__ void k_zero(const float* __restrict__ W0, const float* __restrict__ W1,
                       const float* __restrict__ W2) {
    int i = blockIdx.x * 256 + threadIdx.x;
    if (i < NN) { g_degin[i] = 0; g_degout[i] = 0; }
    if (i < NG) g_gcnt[i] = 0;
    if (i < NG * DD) g_hg[i] = 0.0f;
    if (i < 3 * DD) { g_sum[i] = 0.0f; g_sq[i] = 0.0f; }
    if (i < (NTILE * 128 - NN) * 32) g_bufX[NN * 32 + i] = make_uint2(0, 0);  // pad rows
    if (i < 3 * 16384) {
        int l = i >> 14, rem = i & 16383;
        int k = rem >> 7, n = rem & 127;
        const float* W = (l == 0) ? W0 : ((l == 1) ? W1 : W2);
        ((__nv_bfloat16*)(g_Wbf + l * 32768))[n * 128 + k] = __float2bfloat16(W[k * 128 + n]);
    }
}

__global__ void k_deg(const int* __restrict__ src, const int* __restrict__ dst,
                      const int* __restrict__ gids) {
    int e = blockIdx.x * 256 + threadIdx.x;
    if (e < NE) {
        atomicAdd(&g_degout[src[e]], 1);
        atomicAdd(&g_degin[dst[e]], 1);
    }
    bool valid = e < NN;
    int g = valid ? gids[e] : -1;
    int g0 = __shfl_sync(0xffffffffu, g, 0);
    if (__all_sync(0xffffffffu, g == g0)) {
        if ((threadIdx.x & 31) == 0 && g0 >= 0) atomicAdd(&g_gcnt[g0], 32);
    } else if (valid) {
        atomicAdd(&g_gcnt[g], 1);
    }
}

__global__ void k_scan1() {
    int tid = threadIdx.x;
    int gid = blockIdx.x * 1024 + tid;
    int v = (gid < NN) ? g_degin[gid] : 0;
    int lane = tid & 31, w = tid >> 5;
    int x = v;
#pragma unroll
    for (int o = 1; o < 32; o <<= 1) {
        int y = __shfl_up_sync(0xffffffffu, x, o);
        if (lane >= o) x += y;
    }
    __shared__ int ws[32];
    if (lane == 31) ws[w] = x;
    __syncthreads();
    if (w == 0) {
        int y = ws[lane];
#pragma unroll
        for (int o = 1; o < 32; o <<= 1) {
            int z = __shfl_up_sync(0xffffffffu, y, o);
            if (lane >= o) y += z;
        }
        ws[lane] = y;
    }
    __syncthreads();
    int incl = x + (w ? ws[w - 1] : 0);
    if (gid < NN) g_off[gid] = incl - v;
    if (tid == 1023) g_part[blockIdx.x] = incl;
}

// finalize offsets + norms (block redundantly scans the 98 partials), then
// fused embed: bufA = bf16(embed[tokens] * norm_src) for this block's nodes
__global__ void k_scan3(const int* __restrict__ tokens, const float* __restrict__ embed) {
    __shared__ int ws[4];
    __shared__ int po;
    __shared__ float snsrc[1024];
    int tid = threadIdx.x;
    int lane = tid & 31, w2 = tid >> 5;
    int v = 0, x = 0;
    if (tid < 128) {
        v = (tid < NBS) ? g_part[tid] : 0;
        x = v;
#pragma unroll
        for (int o = 1; o < 32; o <<= 1) {
            int y = __shfl_up_sync(0xffffffffu, x, o);
            if (lane >= o) x += y;
        }
        if (lane == 31) ws[w2] = x;
    }
    __syncthreads();
    if (tid < 128) {
        int add = 0;
#pragma unroll
        for (int i = 0; i < 4; i++) if (i < w2) add += ws[i];
        if (tid == (int)blockIdx.x) po = x - v + add;   // exclusive prefix for this block
    }
    __syncthreads();
    int base = blockIdx.x * 1024;
    int gid = base + tid;
    float ns = 0.0f;
    if (gid < NN) {
        int o = g_off[gid] + po;
        g_off[gid] = o;
        g_cur[gid] = o;
        ns = rsqrtf((float)max(g_degout[gid], 1));
        g_nsrc[gid] = ns;
        g_ndst[gid] = rsqrtf((float)max(g_degin[gid], 1));
    }
    snsrc[tid] = ns;
    __syncthreads();
    // fused embed: warp per node, 32 nodes per warp
    for (int i = 0; i < 32; i++) {
        int nid = base + w2 * 32 + i;
        if (nid >= NN) break;
        int t = tokens[nid];
        float4 e = ((const float4*)embed)[t * 32 + lane];
        float nsv = snsrc[w2 * 32 + i];
        g_bufA[nid * 32 + lane] = pack_bf16x4(e.x * nsv, e.y * nsv, e.z * nsv, e.w * nsv);
    }
}

__global__ void k_scatter(const int* __restrict__ src, const int* __restrict__ dst) {
    int e = blockIdx.x * 256 + threadIdx.x;
    if (e < NE) {
        int d = dst[e];
        int pos = atomicAdd(&g_cur[d], 1);
        g_csr[pos] = src[e];
    }
}

// ---------------- per-layer kernels ----------------
// agg[v] = norm_dst[v] * sum bufA[src]; bf16 output row-major into g_bufX
__global__ void k_agg() {
    int nid = blockIdx.x * 8 + (threadIdx.x >> 5);
    int lane = threadIdx.x & 31;
    if (nid >= NN) return;
    int off = g_off[nid];
    int deg = g_degin[nid];
    float2 a0 = make_float2(0, 0), a1 = make_float2(0, 0);
    float2 b0 = make_float2(0, 0), b1 = make_float2(0, 0);
    for (int base = 0; base < deg; base += 32) {
        int n = min(32, deg - base);
        int idx = (base + lane < deg) ? g_csr[off + base + lane] : 0;
        int j = 0;
        for (; j + 3 < n; j += 4) {
            int s0 = __shfl_sync(0xffffffffu, idx, j);
            int s1 = __shfl_sync(0xffffffffu, idx, j + 1);
            int s2 = __shfl_sync(0xffffffffu, idx, j + 2);
            int s3 = __shfl_sync(0xffffffffu, idx, j + 3);
            uint2 m0 = g_bufA[s0 * 32 + lane];
            uint2 m1 = g_bufA[s1 * 32 + lane];
            uint2 m2 = g_bufA[s2 * 32 + lane];
            uint2 m3 = g_bufA[s3 * 32 + lane];
            addmsg(a0, a1, m0);
            addmsg(b0, b1, m1);
            addmsg(a0, a1, m2);
            addmsg(b0, b1, m3);
        }
        for (; j < n; j++) {
            int s0 = __shfl_sync(0xffffffffu, idx, j);
            uint2 m0 = g_bufA[s0 * 32 + lane];
            addmsg(a0, a1, m0);
        }
    }
    float nd = g_ndst[nid];
    g_bufX[nid * 32 + lane] = pack_bf16x4((a0.x + b0.x) * nd, (a0.y + b0.y) * nd,
                                          (a1.x + b1.x) * nd, (a1.y + b1.y) * nd);
}

// ---------------- mma.sync GEMM: bufB(bf16) = X @ W + b, fused BN stats ----------------
// 256 threads = 8 warps; block tile 128 rows x 128 cols; K in 2 halves of 64.
#define XST 144   // padded smem row stride bytes (128B data + 16) -> conflict-free ldmatrix

__global__ __launch_bounds__(256) void k_gemm_mma(int layer, const float* __restrict__ bias) {
    __shared__ __align__(16) char Xs[128 * XST];
    __shared__ __align__(16) char Wt[128 * XST];
    __shared__ float sS[DD], sQ[DD], sB[DD];
    int tid = threadIdx.x, lane = tid & 31, w = tid >> 5;
    int base = blockIdx.x * 128;
    if (tid < DD) { sS[tid] = 0.0f; sQ[tid] = 0.0f; sB[tid] = bias[tid]; }

    float d[16][4];
#pragma unroll
    for (int t = 0; t < 16; t++)
#pragma unroll
        for (int j = 0; j < 4; j++) d[t][j] = 0.0f;

    const uint4* Xg = (const uint4*)g_bufX + (size_t)base * 16;   // 16 uint4 per row
    const uint4* Wg = (const uint4*)(g_Wbf + layer * 32768);

    int wrow = w * 16;
    uint32_t a_base = smem_u32(Xs + (wrow + (lane & 15)) * XST + (lane >> 4) * 16);
    // B x4 across two adjacent n-tiles: lanes 0-7 m0 (tile t, ksub0), 8-15 m1 (t, ksub1),
    // 16-23 m2 (t+1, ksub0), 24-31 m3 (t+1, ksub1)
    uint32_t b_base = smem_u32(Wt + ((lane & 7) + ((lane >> 4) << 3)) * XST
                               + ((lane >> 3) & 1) * 16);

#pragma unroll
    for (int kh = 0; kh < 2; kh++) {
        // stage 64-k half of X and W: 1024 uint4 each, 256 threads x 4
#pragma unroll
        for (int i = 0; i < 4; i++) {
            int f = tid + i * 256;
            int r = f >> 3, j = f & 7;
            *(uint4*)(Xs + r * XST + j * 16) = Xg[r * 16 + kh * 8 + j];
            *(uint4*)(Wt + r * XST + j * 16) = Wg[r * 16 + kh * 8 + j];
        }
        __syncthreads();
#pragma unroll
        for (int ks = 0; ks < 4; ks++) {
            uint32_t a0, a1, a2, a3;
            asm volatile("ldmatrix.sync.aligned.m8n8.x4.shared.b16 {%0,%1,%2,%3}, [%4];"
                         : "=r"(a0), "=r"(a1), "=r"(a2), "=r"(a3)
                         : "r"(a_base + ks * 32));
#pragma unroll
            for (int tt = 0; tt < 8; tt++) {
                uint32_t b0, b1, b2, b3;
                asm volatile("ldmatrix.sync.aligned.m8n8.x4.shared.b16 {%0,%1,%2,%3}, [%4];"
                             : "=r"(b0), "=r"(b1), "=r"(b2), "=r"(b3)
                             : "r"(b_base + tt * 16 * XST + ks * 32));
                int t0 = tt * 2;
                asm volatile(
                    "mma.sync.aligned.m16n8k16.row.col.f32.bf16.bf16.f32 "
                    "{%0,%1,%2,%3}, {%4,%5,%6,%7}, {%8,%9}, {%0,%1,%2,%3};"
                    : "+f"(d[t0][0]), "+f"(d[t0][1]), "+f"(d[t0][2]), "+f"(d[t0][3])
                    : "r"(a0), "r"(a1), "r"(a2), "r"(a3), "r"(b0), "r"(b1));
                asm volatile(
                    "mma.sync.aligned.m16n8k16.row.col.f32.bf16.bf16.f32 "
                    "{%0,%1,%2,%3}, {%4,%5,%6,%7}, {%8,%9}, {%0,%1,%2,%3};"
                    : "+f"(d[t0 + 1][0]), "+f"(d[t0 + 1][1]), "+f"(d[t0 + 1][2]), "+f"(d[t0 + 1][3])
                    : "r"(a0), "r"(a1), "r"(a2), "r"(a3), "r"(b2), "r"(b3));
            }
        }
        __syncthreads();
    }

    // epilogue: bias + bf16 store + per-column stats (stats from fp32 values)
    int r0 = base + wrow + (lane >> 2);
    int r1 = r0 + 8;
    bool v0 = r0 < NN, v1 = r1 < NN;
    unsigned* outB = (unsigned*)g_bufB;
#pragma unroll
    for (int t = 0; t < 16; t++) {
        int c0 = t * 8 + (lane & 3) * 2;
        float bb0 = sB[c0], bb1 = sB[c0 + 1];
        float d0 = v0 ? d[t][0] + bb0 : 0.0f;
        float d1 = v0 ? d[t][1] + bb1 : 0.0f;
        float d2 = v1 ? d[t][2] + bb0 : 0.0f;
        float d3 = v1 ? d[t][3] + bb1 : 0.0f;
        if (v0) {
            __nv_bfloat162 h = __floats2bfloat162_rn(d0, d1);
            outB[(size_t)r0 * 64 + (c0 >> 1)] = *reinterpret_cast<unsigned*>(&h);
        }
        if (v1) {
            __nv_bfloat162 h = __floats2bfloat162_rn(d2, d3);
            outB[(size_t)r1 * 64 + (c0 >> 1)] = *reinterpret_cast<unsigned*>(&h);
        }
        float s0 = d0 + d2, s1 = d1 + d3;
        float q0 = d0 * d0 + d2 * d2, q1 = d1 * d1 + d3 * d3;
#pragma unroll
        for (int o = 4; o < 32; o <<= 1) {
            s0 += __shfl_xor_sync(0xffffffffu, s0, o);
            s1 += __shfl_xor_sync(0xffffffffu, s1, o);
            q0 += __shfl_xor_sync(0xffffffffu, q0, o);
            q1 += __shfl_xor_sync(0xffffffffu, q1, o);
        }
        if (lane < 4) {
            atomicAdd(&sS[c0], s0);
            atomicAdd(&sS[c0 + 1], s1);
            atomicAdd(&sQ[c0], q0);
            atomicAdd(&sQ[c0 + 1], q1);
        }
    }
    __syncthreads();
    if (tid < DD) {
        atomicAdd(&g_sum[layer * DD + tid], sS[tid]);
        atomicAdd(&g_sq[layer * DD + tid], sQ[tid]);
    }
}

// layers 0/1: bufA = bf16(relu(bn(bufB)) * norm_src)  (BN affine computed per block)
__global__ void k_apply(int layer, const float* __restrict__ gamma,
                        const float* __restrict__ beta) {
    __shared__ __align__(16) float ssc[DD], ssh[DD];
    int tid = threadIdx.x;
    bn_affine(layer, gamma, beta, ssc, ssh, tid);
    __syncthreads();
    int idx = blockIdx.x * 256 + tid;
    if (idx >= NN * 32) return;
    int v = idx >> 5, q = idx & 31;
    float4 y = unpack_bf16x4(g_bufB[idx]);
    float4 sc = ((const float4*)ssc)[q];
    float4 sh = ((const float4*)ssh)[q];
    float ns = g_nsrc[v];
    float rx = fmaxf(fmaf(y.x, sc.x, sh.x), 0.0f) * ns;
    float ry = fmaxf(fmaf(y.y, sc.y, sh.y), 0.0f) * ns;
    float rz = fmaxf(fmaf(y.z, sc.z, sh.z), 0.0f) * ns;
    float rw = fmaxf(fmaf(y.w, sc.w, sh.w), 0.0f) * ns;
    g_bufA[idx] = pack_bf16x4(rx, ry, rz, rw);
}

// layer 2: relu(bn(bufB)) pooled per graph (warp-reduced; graph_ids sorted)
__global__ void k_pool(const int* __restrict__ gids, const float* __restrict__ gamma,
                       const float* __restrict__ beta) {
    __shared__ __align__(16) float ssc[DD], ssh[DD];
    int tid = threadIdx.x;
    bn_affine(2, gamma, beta, ssc, ssh, tid);
    __syncthreads();
    int w = tid >> 5, lane = tid & 31;
    int v = blockIdx.x * 32 + lane;
    bool valid = v < NN;
    int g = valid ? gids[v] : 0;
    int g0 = __shfl_sync(0xffffffffu, g, 0);
    bool uni = __all_sync(0xffffffffu, valid && g == g0);
#pragma unroll
    for (int qq = 0; qq < 4; qq++) {
        int q = w * 4 + qq;
        float4 val = make_float4(0, 0, 0, 0);
        if (valid) {
            float4 y = unpack_bf16x4(g_bufB[v * 32 + q]);
            float4 sc = ((const float4*)ssc)[q];
            float4 sh = ((const float4*)ssh)[q];
            val.x = fmaxf(fmaf(y.x, sc.x, sh.x), 0.0f);
            val.y = fmaxf(fmaf(y.y, sc.y, sh.y), 0.0f);
            val.z = fmaxf(fmaf(y.z, sc.z, sh.z), 0.0f);
            val.w = fmaxf(fmaf(y.w, sc.w, sh.w), 0.0f);
        }
        if (uni) {
#pragma unroll
            for (int o = 16; o; o >>= 1) {
                val.x += __shfl_xor_sync(0xffffffffu, val.x, o);
                val.y += __shfl_xor_sync(0xffffffffu, val.y, o);
                val.z += __shfl_xor_sync(0xffffffffu, val.z, o);
                val.w += __shfl_xor_sync(0xffffffffu, val.w, o);
            }
            if (lane == 0) {
                float* p = &g_hg[g0 * DD + q * 4];
                atomicAdd(p + 0, val.x);
                atomicAdd(p + 1, val.y);
                atomicAdd(p + 2, val.z);
                atomicAdd(p + 3, val.w);
            }
        } else if (valid) {
            float* p = &g_hg[g * DD + q * 4];
            atomicAdd(p + 0, val.x);
            atomicAdd(p + 1, val.y);
            atomicAdd(p + 2, val.z);
            atomicAdd(p + 3, val.w);
        }
    }
}

// head: mean -> fc1 relu -> fc2   (one block per graph, 64 threads)
__global__ void k_head(const float* __restrict__ fcW1, const float* __restrict__ fcb1,
                       const float* __restrict__ fcW2, const float* __restrict__ fcb2,
                       float* __restrict__ out) {
    int g = blockIdx.x, t = threadIdx.x;
    __shared__ float hg[DD];
    __shared__ float s0[64], s1[64];
    float inv = 1.0f / (float)max(g_gcnt[g], 1);
    for (int k = t; k < DD; k += 64) hg[k] = g_hg[g * DD + k] * inv;
    __syncthreads();
    float z = fcb1[t];
#pragma unroll
    for (int k = 0; k < DD; k++) z = fmaf(hg[k], fcW1[k * 64 + t], z);
    z = fmaxf(z, 0.0f);
    s0[t] = z * fcW2[t * 2 + 0];
    s1[t] = z * fcW2[t * 2 + 1];
    __syncthreads();
    if (t == 0) {
        float a = 0.0f, b = 0.0f;
        for (int j = 0; j < 64; j++) { a += s0[j]; b += s1[j]; }
        out[g * 2 + 0] = a + fcb2[0];
        out[g * 2 + 1] = b + fcb2[1];
    }
}

// ---------------- launch ----------------
extern "C" void kernel_launch(void* const* d_in, const int* in_sizes, int n_in,
                              void* d_out, int out_size) {
    const int* tokens = (const int*)d_in[0];
    const int* src    = (const int*)d_in[1];
    const int* dst    = (const int*)d_in[2];
    const int* gids   = (const int*)d_in[3];
    const float* embed = (const float*)d_in[4];
    const float* W[3]  = {(const float*)d_in[5], (const float*)d_in[9],  (const float*)d_in[13]};
    const float* bW[3] = {(const float*)d_in[6], (const float*)d_in[10], (const float*)d_in[14]};
    const float* ga[3] = {(const float*)d_in[7], (const float*)d_in[11], (const float*)d_in[15]};
    const float* be[3] = {(const float*)d_in[8], (const float*)d_in[12], (const float*)d_in[16]};
    const float* fcW1 = (const float*)d_in[17];
    const float* fcb1 = (const float*)d_in[18];
    const float* fcW2 = (const float*)d_in[19];
    const float* fcb2 = (const float*)d_in[20];
    float* out = (float*)d_out;

    k_zero<<<391, 256>>>(W[0], W[1], W[2]);
    k_deg<<<6250, 256>>>(src, dst, gids);
    k_scan1<<<NBS, 1024>>>();
    k_scan3<<<NBS, 1024>>>(tokens, embed);
    k_scatter<<<6250, 256>>>(src, dst);

    for (int l = 0; l < 3; l++) {
        k_agg<<<12500, 256>>>();
        k_gemm_mma<<<NTILE, 256>>>(l, bW[l]);
        if (l < 2)
            k_apply<<<12500, 256>>>(l, ga[l], be[l]);
        else
            k_pool<<<3125, 256>>>(gids, ga[2], be[2]);
    }
    k_head<<<64, 64>>>(fcW1, fcb1, fcW2, fcb2, out);
}